// round 1
// baseline (speedup 1.0000x reference)
#include <cuda_runtime.h>

// C51 categorical projection.
// reward [BS], probs [BS,51], not_done [BS] -> new_probs [BS,51]
//
// b(j) = clamp((reward + 0.99*nd*(VMIN + 0.4*j) - VMIN)/0.4, 0, 50)
//      = clamp(c + s*j, 0, 50),   s = 0.99*nd,  c = 2.5*(reward + 10 - 10*s)
// (float(1/0.4f) == 2.5f exactly; deviation vs reference division ~1e-8 rel)
//
// floor(b) is nondecreasing in j with step in {0,1} (s < 1), so the two live
// output bins are kept in registers and emitted with a single STS each.

constexpr int A    = 51;    // atoms
constexpr int RPB  = 256;   // rows per block
constexpr int PAD  = RPB + 1;           // 257: odd word stride -> conflict-free
constexpr int SEG  = A * PAD;           // floats per smem region
constexpr int SMEM_BYTES = 2 * SEG * (int)sizeof(float);  // 104856 B

__global__ __launch_bounds__(RPB)
void cat_proj_kernel(const float* __restrict__ reward,
                     const float* __restrict__ probs,
                     const float* __restrict__ not_done,
                     float* __restrict__ out,
                     int bs)
{
    extern __shared__ float sm[];
    float* stage = sm;        // [a][r] stride PAD
    float* acc   = sm + SEG;  // [a][r] stride PAD

    const int tid   = threadIdx.x;
    const int rbase = blockIdx.x * RPB;       // first row of this block
    const int ebase = rbase * A;              // first prob element
    const int n_el  = bs * A;

    // zero accumulator region
    for (int i = tid; i < SEG; i += RPB)
        acc[i] = 0.0f;

    // stage probs: coalesced global read, transposed smem store
    for (int i = tid; i < A * RPB; i += RPB) {
        int g = ebase + i;
        float v = (g < n_el) ? probs[g] : 0.0f;
        int r = i / A;
        int a = i - r * A;
        stage[a * PAD + r] = v;
    }
    __syncthreads();

    const int grow = rbase + tid;
    if (grow < bs) {
        const float rw = reward[grow];
        const float s  = 0.99f * not_done[grow];
        const float c  = 2.5f * (rw + 10.0f - 10.0f * s);

        // j = 0
        float p  = stage[tid];
        float b  = fminf(fmaxf(c, 0.0f), 50.0f);
        float lf = floorf(b);
        int   k  = (int)lf;
        float wu = (b - lf) * p;
        float aK  = p - wu;   // mass for bin k
        float aK1 = wu;       // mass for bin k+1

        #pragma unroll
        for (int j = 1; j < A; j++) {
            p  = stage[j * PAD + tid];
            b  = fminf(fmaxf(fmaf(s, (float)j, c), 0.0f), 50.0f);
            lf = floorf(b);
            int li = (int)lf;          // li in {k, k+1}
            wu = (b - lf) * p;
            float wl = p - wu;
            if (li != k) {             // bin k is finished: emit once
                acc[k * PAD + tid] = aK;
                aK  = aK1;
                aK1 = 0.0f;
                k   = li;
            }
            aK  += wl;
            aK1 += wu;
        }
        // final emits. If k == 50, aK1 is provably 0, and this order
        // (aK1 first, then aK) makes the k==50 overwrite benign.
        int k1 = k + 1; if (k1 > A - 1) k1 = A - 1;
        acc[k1 * PAD + tid] = aK1;
        acc[k  * PAD + tid] = aK;
    }
    __syncthreads();

    // copy out: transposed smem read, coalesced global store
    for (int i = tid; i < A * RPB; i += RPB) {
        int g = ebase + i;
        if (g < n_el) {
            int r = i / A;
            int a = i - r * A;
            out[g] = acc[a * PAD + r];
        }
    }
}

extern "C" void kernel_launch(void* const* d_in, const int* in_sizes, int n_in,
                              void* d_out, int out_size)
{
    const float* reward   = (const float*)d_in[0];
    const float* probs    = (const float*)d_in[1];
    const float* not_done = (const float*)d_in[2];
    float* out = (float*)d_out;

    const int bs = in_sizes[0];
    const int grid = (bs + RPB - 1) / RPB;

    cudaFuncSetAttribute(cat_proj_kernel,
                         cudaFuncAttributeMaxDynamicSharedMemorySize,
                         SMEM_BYTES);
    cat_proj_kernel<<<grid, RPB, SMEM_BYTES>>>(reward, probs, not_done, out, bs);
}

// round 2
// speedup vs baseline: 1.7713x; 1.7713x over previous
#include <cuda_runtime.h>

// C51 categorical projection.
// reward [BS], probs [BS,51], not_done [BS] -> new_probs [BS,51]
//
// b(j) = clamp(c + s*j, 0, 50),  s = 0.99*nd,  c = 2.5*(reward + 10 - 10*s)
//
// floor(b) is nondecreasing in j with step in {0,1} (s < 1), so the two live
// output bins live in registers. Emission is BRANCHLESS: since k only moves
// forward, an unconditional STS acc[k]=aK each iteration is correct (the last
// store before k advances carries the completed bin value; earlier partial
// stores are overwritten).

constexpr int A    = 51;    // atoms
constexpr int RPB  = 256;   // rows per block
constexpr int PAD  = RPB + 1;           // 257: odd word stride -> conflict-free transpose
constexpr int SEG  = A * PAD;           // floats per smem region
constexpr int SMEM_BYTES = 2 * SEG * (int)sizeof(float);  // 104856 B

__global__ __launch_bounds__(RPB, 2)
void cat_proj_kernel(const float* __restrict__ reward,
                     const float* __restrict__ probs,
                     const float* __restrict__ not_done,
                     float* __restrict__ out,
                     int bs)
{
    extern __shared__ float sm[];
    float* stage = sm;        // [a][r] stride PAD
    float* acc   = sm + SEG;  // [a][r] stride PAD

    const int tid   = threadIdx.x;
    const int rbase = blockIdx.x * RPB;       // first row of this block
    const int ebase = rbase * A;              // first prob element
    const int n_el  = bs * A;
    const int grow  = rbase + tid;

    // per-row scalars loaded early (overlap with staging)
    float rw = 0.0f, nd = 0.0f;
    if (grow < bs) { rw = reward[grow]; nd = not_done[grow]; }

    // zero accumulator region
    #pragma unroll
    for (int k = 0; k < A; k++)
        acc[k * PAD + tid] = 0.0f;
    if (tid < A) acc[tid * PAD + RPB] = 0.0f;   // pad column (never read, but keep clean)

    // stage probs: coalesced global read, transposed smem store
    #pragma unroll
    for (int it = 0; it < A; it++) {
        int i = tid + it * RPB;
        int g = ebase + i;
        float v = (g < n_el) ? probs[g] : 0.0f;
        int r = i / A;
        int a = i - r * A;
        stage[a * PAD + r] = v;
    }
    __syncthreads();

    if (grow < bs) {
        const float s = 0.99f * nd;
        const float c = 2.5f * (rw + 10.0f - 10.0f * s);

        // prefetch entire row into registers: 51 independent LDS, issued
        // back-to-back (throughput-bound, latency overlapped)
        float pv[A];
        #pragma unroll
        for (int j = 0; j < A; j++)
            pv[j] = stage[j * PAD + tid];

        // j = 0
        float b  = fminf(fmaxf(c, 0.0f), 50.0f);
        float lf = floorf(b);
        int   k  = (int)lf;
        float wu = (b - lf) * pv[0];
        float aK  = pv[0] - wu;   // mass for bin k
        float aK1 = wu;           // mass for bin k+1

        #pragma unroll
        for (int j = 1; j < A; j++) {
            b  = fminf(fmaxf(fmaf(s, (float)j, c), 0.0f), 50.0f);
            lf = floorf(b);
            int li = (int)lf;               // li in {k, k+1}
            wu = (b - lf) * pv[j];
            float wl = pv[j] - wu;

            // unconditional emit of the currently-open bin (idempotent until
            // k advances; the store in the advancing iteration is final)
            acc[k * PAD + tid] = aK;

            bool adv = (li != k);
            aK  = adv ? aK1  : aK;
            aK1 = adv ? 0.0f : aK1;
            k   = li;

            aK  += wl;
            aK1 += wu;
        }
        // final emits. If k == 50, aK1 is provably 0; this order makes the
        // k==50 overwrite benign.
        int k1 = k + 1; if (k1 > A - 1) k1 = A - 1;
        acc[k1 * PAD + tid] = aK1;
        acc[k  * PAD + tid] = aK;
    }
    __syncthreads();

    // copy out: transposed smem read, coalesced global store
    #pragma unroll
    for (int it = 0; it < A; it++) {
        int i = tid + it * RPB;
        int g = ebase + i;
        if (g < n_el) {
            int r = i / A;
            int a = i - r * A;
            out[g] = acc[a * PAD + r];
        }
    }
}

extern "C" void kernel_launch(void* const* d_in, const int* in_sizes, int n_in,
                              void* d_out, int out_size)
{
    const float* reward   = (const float*)d_in[0];
    const float* probs    = (const float*)d_in[1];
    const float* not_done = (const float*)d_in[2];
    float* out = (float*)d_out;

    const int bs = in_sizes[0];
    const int grid = (bs + RPB - 1) / RPB;

    cudaFuncSetAttribute(cat_proj_kernel,
                         cudaFuncAttributeMaxDynamicSharedMemorySize,
                         SMEM_BYTES);
    cat_proj_kernel<<<grid, RPB, SMEM_BYTES>>>(reward, probs, not_done, out, bs);
}